// round 15
// baseline (speedup 1.0000x reference)
#include <cuda_runtime.h>
#include <cuda_fp16.h>
#include <cstdint>

#define BB 8
#define NQ 1024
#define NKV 2048
#define QD 1024
#define CD 768
#define INNER 1024
#define NH 16
#define HD 64

// Scratch (allocation-free rule: __device__ globals) — fp16
__device__ __half g_q[BB * NQ * INNER];
__device__ __half g_kv[BB * NKV * 2 * INNER];
__device__ __half g_att[BB * NQ * INNER];
__device__ __half g_wqT[INNER * QD];             // [N,K]
__device__ __half g_wkvT[2 * INNER * CD];        // [N,K]
__device__ __half g_woutT[QD * INNER];           // [N,K]
__device__ unsigned g_cnt[64];                   // per-(b,qtile) completion counters

// ---------------------------------------------------------------------------
// helpers
// ---------------------------------------------------------------------------
__device__ __forceinline__ uint32_t smem_u32(const void* p) {
    uint32_t a;
    asm("{ .reg .u64 t; cvta.to.shared.u64 t, %1; cvt.u32.u64 %0, t; }"
        : "=r"(a) : "l"(p));
    return a;
}
__device__ __forceinline__ float ex2(float x) {
    float r;
    asm("ex2.approx.f32 %0, %1;" : "=f"(r) : "f"(x));
    return r;
}
__device__ __forceinline__ uint32_t h2u(__half2 v) { return *(uint32_t*)&v; }

#define CP_ASYNC16(dst, src) \
    asm volatile("cp.async.cg.shared.global [%0], [%1], 16;" :: "r"(dst), "l"(src))
#define CP_COMMIT() asm volatile("cp.async.commit_group;")
#define CP_WAIT1()  asm volatile("cp.async.wait_group 1;")
#define CP_WAIT0()  asm volatile("cp.async.wait_group 0;")

__device__ __forceinline__ void mma_f16(float* c, const uint32_t* a, const uint32_t* b) {
    asm volatile(
        "mma.sync.aligned.m16n8k16.row.col.f32.f16.f16.f32 "
        "{%0,%1,%2,%3}, {%4,%5,%6,%7}, {%8,%9}, {%0,%1,%2,%3};"
        : "+f"(c[0]), "+f"(c[1]), "+f"(c[2]), "+f"(c[3])
        : "r"(a[0]), "r"(a[1]), "r"(a[2]), "r"(a[3]), "r"(b[0]), "r"(b[1]));
}
#define LDSM_X4(r0, r1, r2, r3, addr) \
    asm volatile("ldmatrix.sync.aligned.m8n8.x4.shared.b16 {%0,%1,%2,%3}, [%4];" \
        : "=r"(r0), "=r"(r1), "=r"(r2), "=r"(r3) : "r"(addr))
#define LDSM_X4_T(r0, r1, r2, r3, addr) \
    asm volatile("ldmatrix.sync.aligned.m8n8.x4.trans.shared.b16 {%0,%1,%2,%3}, [%4];" \
        : "=r"(r0), "=r"(r1), "=r"(r2), "=r"(r3) : "r"(addr))

// ---------------------------------------------------------------------------
// Fused transpose of all 3 weights + counter zeroing.
// out[C][R] = half(in[R][C]^T)
// ---------------------------------------------------------------------------
__global__ __launch_bounds__(256) void transpose3_k(
    const float* __restrict__ w_q, __half* __restrict__ wqT,
    const float* __restrict__ w_kv, __half* __restrict__ wkvT,
    const float* __restrict__ w_out, __half* __restrict__ woutT)
{
    if (blockIdx.z == 0 && blockIdx.x == 0 && blockIdx.y == 0) {
        int t = threadIdx.y * 32 + threadIdx.x;
        if (t < 64) g_cnt[t] = 0u;
    }
    const float* in;
    __half* out;
    int R, C;
    if (blockIdx.z == 0)      { in = w_q;   out = wqT;   R = QD;    C = INNER; }
    else if (blockIdx.z == 1) { in = w_kv;  out = wkvT;  R = CD;    C = 2 * INNER; }
    else                      { in = w_out; out = woutT; R = INNER; C = QD; }
    if ((int)blockIdx.x * 32 >= C || (int)blockIdx.y * 32 >= R) return;

    __shared__ float t[32][33];
    int x = blockIdx.x * 32 + threadIdx.x;
    int y0 = blockIdx.y * 32;
#pragma unroll
    for (int j = 0; j < 32; j += 8)
        t[threadIdx.y + j][threadIdx.x] = in[(size_t)(y0 + threadIdx.y + j) * C + x];
    __syncthreads();
    int ox = y0 + threadIdx.x;
#pragma unroll
    for (int j = 0; j < 32; j += 8)
        out[(size_t)(blockIdx.x * 32 + threadIdx.y + j) * R + ox] =
            __float2half(t[threadIdx.x][threadIdx.y + j]);
}

// ---------------------------------------------------------------------------
// Shared fp16 GEMM body (unchanged R13/14 best).
// ---------------------------------------------------------------------------
#define LDTH 40
#define STAGE_H (128 * LDTH)
#define STAGE_BY (STAGE_H * 2)
#define GEMM_SMEM (6 * STAGE_BY)      // 61440 B

template <int RA, int HOUT>
__device__ __forceinline__ void gemm_body(
    const void* __restrict__ Av, const __half* __restrict__ Bt,
    void* __restrict__ Cv, int M, int N, int K, const float* __restrict__ bias,
    int m0, int n0, __half* sh)
{
    uint32_t sbase = smem_u32(sh);
    const int tid = threadIdx.x;
    const int wid = tid >> 5, lane = tid & 31;
    const int g = lane >> 2, tig = lane & 3;
    const int wm = wid & 1, wn = wid >> 1;

    const float*  Af = (const float*)Av;
    const __half* Ah = (const __half*)Av;

    const int lm = lane >> 3;
    const int arow = (lm & 1) * 8 + (lane & 7);
    const int acol = (lm >> 1) * 8;
    const int brow = ((lm >> 1) & 1) * 8 + (lane & 7);
    const int bcol = (lm & 1) * 8;

    float acc[4][4][4];
#pragma unroll
    for (int mi = 0; mi < 4; mi++)
#pragma unroll
        for (int ni = 0; ni < 4; ni++)
#pragma unroll
            for (int j = 0; j < 4; j++) acc[mi][ni][j] = 0.f;

    const int S = K / 32;

    const int lrow = tid >> 3;
    const int lc4 = tid & 7;
    float4 areg[4];
    auto ldg_A = [&](int s) {
        const float* Ag = Af + (size_t)m0 * K + s * 32;
#pragma unroll
        for (int i = 0; i < 4; i++) {
            int row = lrow + i * 32;
            areg[i] = *(const float4*)(Ag + (size_t)row * K + lc4 * 4);
        }
    };
    auto sts_A = [&](int s) {
        __half* aB = sh + (s % 3) * STAGE_H;
#pragma unroll
        for (int i = 0; i < 4; i++) {
            int row = lrow + i * 32;
            float4 v = areg[i];
            uint2 u = make_uint2(h2u(__floats2half2_rn(v.x, v.y)),
                                 h2u(__floats2half2_rn(v.z, v.w)));
            *(uint2*)(aB + row * LDTH + lc4 * 4) = u;
        }
    };
    const int hrow = tid >> 1;
    const int hc = tid & 1;
    auto cpa_A = [&](int s) {
        const __half* Ag = Ah + (size_t)m0 * K + s * 32;
        uint32_t aB = sbase + (s % 3) * STAGE_BY;
#pragma unroll
        for (int i = 0; i < 2; i++) {
            int c = hc * 2 + i;
            CP_ASYNC16(aB + (uint32_t)(hrow * 80 + c * 16),
                       Ag + (size_t)hrow * K + c * 8);
        }
    };
    auto cp_B = [&](int s) {
        const __half* Bg = Bt + (size_t)n0 * K + s * 32;
        uint32_t bB = sbase + 3 * STAGE_BY + (s % 3) * STAGE_BY;
#pragma unroll
        for (int i = 0; i < 2; i++) {
            int c = hc * 2 + i;
            CP_ASYNC16(bB + (uint32_t)(hrow * 80 + c * 16),
                       Bg + (size_t)hrow * K + c * 8);
        }
        CP_COMMIT();
    };

    if (RA) {
        ldg_A(0); cp_B(0); sts_A(0);
        ldg_A(1); cp_B(1); sts_A(1);
    } else {
        cpa_A(0); cp_B(0);
        cpa_A(1); cp_B(1);
    }

    for (int s = 0; s < S; s++) {
        if (s + 1 < S) CP_WAIT1();
        else           CP_WAIT0();
        __syncthreads();

        if (s + 2 < S) {
            if (RA) ldg_A(s + 2); else cpa_A(s + 2);
            cp_B(s + 2);
        }

        uint32_t Asb = sbase + (s % 3) * STAGE_BY + (wm * 64) * (LDTH * 2);
        uint32_t Bsb = sbase + 3 * STAGE_BY + (s % 3) * STAGE_BY + (wn * 32) * (LDTH * 2);

#pragma unroll
        for (int kk = 0; kk < 32; kk += 16) {
            uint32_t a[4][4], b[4][2];
#pragma unroll
            for (int mi = 0; mi < 4; mi++) {
                uint32_t addr = Asb + (uint32_t)(((mi * 16 + arow) * LDTH + kk + acol) * 2);
                LDSM_X4(a[mi][0], a[mi][1], a[mi][2], a[mi][3], addr);
            }
#pragma unroll
            for (int nj = 0; nj < 2; nj++) {
                uint32_t addr = Bsb + (uint32_t)(((nj * 16 + brow) * LDTH + kk + bcol) * 2);
                LDSM_X4(b[2 * nj][0], b[2 * nj][1], b[2 * nj + 1][0], b[2 * nj + 1][1], addr);
            }
#pragma unroll
            for (int mi = 0; mi < 4; mi++)
#pragma unroll
                for (int ni = 0; ni < 4; ni++)
                    mma_f16(acc[mi][ni], a[mi], b[ni]);
        }

        if (RA && (s + 2 < S)) sts_A(s + 2);
    }

#pragma unroll
    for (int mi = 0; mi < 4; mi++) {
        int r0 = m0 + wm * 64 + mi * 16 + g;
#pragma unroll
        for (int ni = 0; ni < 4; ni++) {
            int c = n0 + wn * 32 + ni * 8 + 2 * tig;
            if (HOUT) {
                __half* Ch = (__half*)Cv;
                *(__half2*)(Ch + (size_t)r0 * N + c) =
                    __floats2half2_rn(acc[mi][ni][0], acc[mi][ni][1]);
                *(__half2*)(Ch + (size_t)(r0 + 8) * N + c) =
                    __floats2half2_rn(acc[mi][ni][2], acc[mi][ni][3]);
            } else {
                float* Cf = (float*)Cv;
                float b0 = bias ? bias[c] : 0.f;
                float b1 = bias ? bias[c + 1] : 0.f;
                *(float2*)(Cf + (size_t)r0 * N + c) =
                    make_float2(acc[mi][ni][0] + b0, acc[mi][ni][1] + b1);
                *(float2*)(Cf + (size_t)(r0 + 8) * N + c) =
                    make_float2(acc[mi][ni][2] + b0, acc[mi][ni][3] + b1);
            }
        }
    }
}

// Fused q-proj + kv-proj (unchanged R14).
#define Q_CTAS 512
#define KV_CTAS 2048

__global__ __launch_bounds__(256, 2) void proj_gemm(
    const float* __restrict__ query, const __half* __restrict__ wqT,
    __half* __restrict__ qout,
    const float* __restrict__ context, const __half* __restrict__ wkvT,
    __half* __restrict__ kvout)
{
    extern __shared__ __half sh[];
    int bid = blockIdx.x;
    if (bid < Q_CTAS) {
        int nt = bid & 7, mt = bid >> 3;
        gemm_body<1, 1>(query, wqT, qout, BB * NQ, INNER, QD, nullptr,
                        mt * 128, nt * 128, sh);
    } else {
        int b2 = bid - Q_CTAS;
        int nt = b2 & 15, mt = b2 >> 4;
        gemm_body<1, 1>(context, wkvT, kvout, BB * NKV, 2 * INNER, CD, nullptr,
                        mt * 128, nt * 128, sh);
    }
}

// ---------------------------------------------------------------------------
// fp16 flash attention body (R9/R13 inner loops) + release counter.
// ---------------------------------------------------------------------------
#define ASTH 72
#define QSCALE (0.125f * 1.4426950408889634f)

__device__ __forceinline__ void attn_body(
    const __half* __restrict__ qb, const __half* __restrict__ kvb,
    __half* __restrict__ ob, __half* sha, int qt, int bh)
{
    uint32_t sbase = smem_u32(sha);

    const int tid = threadIdx.x;
    const int w = tid >> 5, lane = tid & 31;
    const int g = lane >> 2, tig = lane & 3;
    const int b = bh >> 4, h = bh & 15;
    const int q0 = qt * 128;

    const int lm = lane >> 3;
    const int brow = ((lm >> 1) & 1) * 8 + (lane & 7);
    const int bcol = (lm & 1) * 8;

    const __half* kbase = kvb + (size_t)b * NKV * (2 * INNER) + h * HD;
    const __half* vbase = kbase + INNER;

    uint32_t qf[4][4];
    {
        const __half* Qp = qb + ((size_t)(b * NQ + q0 + w * 16 + g)) * INNER + h * HD;
        const __half2 qs = __float2half2_rn(QSCALE);
#pragma unroll
        for (int kt = 0; kt < 4; kt++) {
            int d = kt * 16 + 2 * tig;
            qf[kt][0] = h2u(__hmul2(*(const __half2*)(Qp + d), qs));
            qf[kt][1] = h2u(__hmul2(*(const __half2*)(Qp + 8 * INNER + d), qs));
            qf[kt][2] = h2u(__hmul2(*(const __half2*)(Qp + d + 8), qs));
            qf[kt][3] = h2u(__hmul2(*(const __half2*)(Qp + 8 * INNER + d + 8), qs));
        }
    }

    float o[8][4];
#pragma unroll
    for (int dt = 0; dt < 8; dt++)
#pragma unroll
        for (int j = 0; j < 4; j++) o[dt][j] = 0.f;
    float l_a = 0.f, l_b = 0.f;

    auto stage_load = [&](int s) {
        const int buf = s & 1;
        const int kv0 = s * 64;
#pragma unroll
        for (int i = 0; i < 4; i++) {
            int slot = tid + i * 256;
            int isK = slot < 512;
            int ls = slot & 511;
            int row = ls >> 3, c8 = ls & 7;
            const __half* src = (isK ? kbase : vbase) + (size_t)(kv0 + row) * (2 * INNER) + c8 * 8;
            uint32_t dst = sbase + (uint32_t)(((isK ? buf : 2 + buf) * 64 + row) * ASTH * 2 + c8 * 16);
            CP_ASYNC16(dst, src);
        }
        CP_COMMIT();
    };

    const int S = NKV / 64;   // 32
    stage_load(0);

    const int vrow = lane & 15;
    const int vcol = ((lane >> 4) & 1) * 8;

    for (int s = 0; s < S; s++) {
        CP_WAIT0();
        __syncthreads();
        if (s + 1 < S) stage_load(s + 1);

        uint32_t Ksb = sbase + (s & 1) * 64 * ASTH * 2;
        const __half* Vsb = sha + (2 + (s & 1)) * 64 * ASTH;

        float sacc[8][4];
#pragma unroll
        for (int nt = 0; nt < 8; nt++)
#pragma unroll
            for (int j = 0; j < 4; j++) sacc[nt][j] = 0.f;

#pragma unroll
        for (int kt = 0; kt < 4; kt++) {
#pragma unroll
            for (int nj = 0; nj < 4; nj++) {
                uint32_t addr = Ksb + (uint32_t)(((nj * 16 + brow) * ASTH + kt * 16 + bcol) * 2);
                uint32_t b0, b1, b2, b3;
                LDSM_X4(b0, b1, b2, b3, addr);
                uint32_t bA[2] = { b0, b1 };
                uint32_t bB2[2] = { b2, b3 };
                mma_f16(sacc[2 * nj], qf[kt], bA);
                mma_f16(sacc[2 * nj + 1], qf[kt], bB2);
            }
        }

        uint32_t ph[8][2];
#pragma unroll
        for (int nt = 0; nt < 8; nt++) {
            float p0 = ex2(sacc[nt][0]);
            float p1 = ex2(sacc[nt][1]);
            float p2 = ex2(sacc[nt][2]);
            float p3 = ex2(sacc[nt][3]);
            l_a += p0 + p1;
            l_b += p2 + p3;
            ph[nt][0] = h2u(__floats2half2_rn(p0, p1));
            ph[nt][1] = h2u(__floats2half2_rn(p2, p3));
        }

#pragma unroll
        for (int kt = 0; kt < 4; kt++) {
            uint32_t a[4] = { ph[2 * kt][0], ph[2 * kt][1],
                              ph[2 * kt + 1][0], ph[2 * kt + 1][1] };
#pragma unroll
            for (int dd = 0; dd < 4; dd++) {
                uint32_t addr = smem_u32(Vsb + (kt * 16 + vrow) * ASTH + dd * 16 + vcol);
                uint32_t r0, r1, r2, r3;
                LDSM_X4_T(r0, r1, r2, r3, addr);
                uint32_t b01[2] = { r0, r1 };
                uint32_t b23[2] = { r2, r3 };
                mma_f16(o[2 * dd], a, b01);
                mma_f16(o[2 * dd + 1], a, b23);
            }
        }
    }

    l_a += __shfl_xor_sync(0xffffffffu, l_a, 1);
    l_a += __shfl_xor_sync(0xffffffffu, l_a, 2);
    l_b += __shfl_xor_sync(0xffffffffu, l_b, 1);
    l_b += __shfl_xor_sync(0xffffffffu, l_b, 2);
    const float inv_a = 1.f / l_a, inv_b = 1.f / l_b;

    __half* oa = ob + ((size_t)(b * NQ + q0 + w * 16 + g)) * INNER + h * HD;
    __half* obp = oa + 8 * INNER;
#pragma unroll
    for (int dt = 0; dt < 8; dt++) {
        int c = dt * 8 + 2 * tig;
        *(__half2*)(oa + c) = __floats2half2_rn(o[dt][0] * inv_a, o[dt][1] * inv_a);
        *(__half2*)(obp + c) = __floats2half2_rn(o[dt][2] * inv_b, o[dt][3] * inv_b);
    }

    // publish: this CTA's att rows are complete
    __syncthreads();
    if (tid == 0) {
        __threadfence();
        atomicAdd(&g_cnt[b * 8 + qt], 1u);
    }
}

// ---------------------------------------------------------------------------
// Fused attention + out-proj. bid < 1024: attention CTA (qt = bid&7, bh = bid>>3).
// bid >= 1024: out tile; spins until its 16 producer CTAs (strictly lower bids)
// have released, then runs the GEMM.
// ---------------------------------------------------------------------------
#define ATTN_CTAS 1024
#define OUT_CTAS 512

__global__ __launch_bounds__(256, 2) void attn_out(
    const __half* __restrict__ q, const __half* __restrict__ kv,
    __half* __restrict__ att, const __half* __restrict__ woutT,
    float* __restrict__ out, const float* __restrict__ bias)
{
    extern __shared__ __half sh[];
    int bid = blockIdx.x;
    if (bid < ATTN_CTAS) {
        attn_body(q, kv, att, sh, bid & 7, bid >> 3);
    } else {
        int ob = bid - ATTN_CTAS;
        int nt = ob & 7, mt = ob >> 3;
        if (threadIdx.x == 0) {
            unsigned* cp = &g_cnt[mt];
            unsigned v;
            do {
                asm volatile("ld.acquire.gpu.global.u32 %0, [%1];"
                             : "=r"(v) : "l"(cp) : "memory");
                if (v < 16u) __nanosleep(128);
            } while (v < 16u);
        }
        __syncthreads();
        gemm_body<0, 0>(att, woutT, out, BB * NQ, QD, INNER, bias,
                        mt * 128, nt * 128, sh);
    }
}

// ---------------------------------------------------------------------------
extern "C" void kernel_launch(void* const* d_in, const int* in_sizes, int n_in,
                              void* d_out, int out_size)
{
    const float* query   = (const float*)d_in[0];
    const float* context = (const float*)d_in[1];
    const float* w_q     = (const float*)d_in[2];
    const float* w_kv    = (const float*)d_in[3];
    const float* w_out   = (const float*)d_in[4];
    const float* b_out   = (const float*)d_in[5];
    float* out = (float*)d_out;

    __half *q, *kv, *att, *wqT, *wkvT, *woutT;
    cudaGetSymbolAddress((void**)&q, g_q);
    cudaGetSymbolAddress((void**)&kv, g_kv);
    cudaGetSymbolAddress((void**)&att, g_att);
    cudaGetSymbolAddress((void**)&wqT, g_wqT);
    cudaGetSymbolAddress((void**)&wkvT, g_wkvT);
    cudaGetSymbolAddress((void**)&woutT, g_woutT);

    cudaFuncSetAttribute(proj_gemm, cudaFuncAttributeMaxDynamicSharedMemorySize, GEMM_SMEM);
    cudaFuncSetAttribute(attn_out, cudaFuncAttributeMaxDynamicSharedMemorySize, GEMM_SMEM);

    // fused weight transposes (fp16, [N,K]) + counter zeroing
    transpose3_k<<<dim3(64, 32, 3), dim3(32, 8)>>>(w_q, wqT, w_kv, wkvT, w_out, woutT);

    // fused q-proj + kv-proj
    proj_gemm<<<Q_CTAS + KV_CTAS, 256, GEMM_SMEM>>>(query, wqT, q, context, wkvT, kv);

    // fused attention + out-proj (counter-synced)
    attn_out<<<ATTN_CTAS + OUT_CTAS, 256, GEMM_SMEM>>>(q, kv, att, woutT, out, b_out);
}

// round 16
// speedup vs baseline: 1.5039x; 1.5039x over previous
#include <cuda_runtime.h>
#include <cuda_fp16.h>
#include <cstdint>

#define BB 8
#define NQ 1024
#define NKV 2048
#define QD 1024
#define CD 768
#define INNER 1024
#define NH 16
#define HD 64

// Scratch (allocation-free rule: __device__ globals) — fp16
__device__ __half g_q[BB * NQ * INNER];
__device__ __half g_kv[BB * NKV * 2 * INNER];
__device__ __half g_att[BB * NQ * INNER];
__device__ __half g_wqT[INNER * QD];             // [N,K]
__device__ __half g_wkvT[2 * INNER * CD];        // [N,K]
__device__ __half g_woutT[QD * INNER];           // [N,K]

// ---------------------------------------------------------------------------
// helpers
// ---------------------------------------------------------------------------
__device__ __forceinline__ uint32_t smem_u32(const void* p) {
    uint32_t a;
    asm("{ .reg .u64 t; cvta.to.shared.u64 t, %1; cvt.u32.u64 %0, t; }"
        : "=r"(a) : "l"(p));
    return a;
}
__device__ __forceinline__ float ex2(float x) {
    float r;
    asm("ex2.approx.f32 %0, %1;" : "=f"(r) : "f"(x));
    return r;
}
__device__ __forceinline__ uint32_t h2u(__half2 v) { return *(uint32_t*)&v; }

#define CP_ASYNC16(dst, src) \
    asm volatile("cp.async.cg.shared.global [%0], [%1], 16;" :: "r"(dst), "l"(src))
#define CP_COMMIT() asm volatile("cp.async.commit_group;")
#define CP_WAIT1()  asm volatile("cp.async.wait_group 1;")
#define CP_WAIT0()  asm volatile("cp.async.wait_group 0;")

__device__ __forceinline__ void mma_f16(float* c, const uint32_t* a, const uint32_t* b) {
    asm volatile(
        "mma.sync.aligned.m16n8k16.row.col.f32.f16.f16.f32 "
        "{%0,%1,%2,%3}, {%4,%5,%6,%7}, {%8,%9}, {%0,%1,%2,%3};"
        : "+f"(c[0]), "+f"(c[1]), "+f"(c[2]), "+f"(c[3])
        : "r"(a[0]), "r"(a[1]), "r"(a[2]), "r"(a[3]), "r"(b[0]), "r"(b[1]));
}
#define LDSM_X4(r0, r1, r2, r3, addr) \
    asm volatile("ldmatrix.sync.aligned.m8n8.x4.shared.b16 {%0,%1,%2,%3}, [%4];" \
        : "=r"(r0), "=r"(r1), "=r"(r2), "=r"(r3) : "r"(addr))
#define LDSM_X4_T(r0, r1, r2, r3, addr) \
    asm volatile("ldmatrix.sync.aligned.m8n8.x4.trans.shared.b16 {%0,%1,%2,%3}, [%4];" \
        : "=r"(r0), "=r"(r1), "=r"(r2), "=r"(r3) : "r"(addr))

// ---------------------------------------------------------------------------
// Fused transpose of all 3 weights: grid.z selects tensor, guards for dims.
// out[C][R] = half(in[R][C]^T)
// ---------------------------------------------------------------------------
__global__ __launch_bounds__(256) void transpose3_k(
    const float* __restrict__ w_q, __half* __restrict__ wqT,
    const float* __restrict__ w_kv, __half* __restrict__ wkvT,
    const float* __restrict__ w_out, __half* __restrict__ woutT)
{
    const float* in;
    __half* out;
    int R, C;
    if (blockIdx.z == 0)      { in = w_q;   out = wqT;   R = QD;    C = INNER; }
    else if (blockIdx.z == 1) { in = w_kv;  out = wkvT;  R = CD;    C = 2 * INNER; }
    else                      { in = w_out; out = woutT; R = INNER; C = QD; }
    if ((int)blockIdx.x * 32 >= C || (int)blockIdx.y * 32 >= R) return;

    __shared__ float t[32][33];
    int x = blockIdx.x * 32 + threadIdx.x;
    int y0 = blockIdx.y * 32;
#pragma unroll
    for (int j = 0; j < 32; j += 8)
        t[threadIdx.y + j][threadIdx.x] = in[(size_t)(y0 + threadIdx.y + j) * C + x];
    __syncthreads();
    int ox = y0 + threadIdx.x;
#pragma unroll
    for (int j = 0; j < 32; j += 8)
        out[(size_t)(blockIdx.x * 32 + threadIdx.y + j) * R + ox] =
            __float2half(t[threadIdx.x][threadIdx.y + j]);
}

// ---------------------------------------------------------------------------
// Shared fp16 GEMM body: C[M,N](tile m0,n0) = A[M,K] @ Bt[N,K]^T (+bias)
// 128x128x32 CTA tile, 8 warps, warp tile 64x32, m16n8k16, ldmatrix.x4.
// 3-deep cp.async pipeline, one __syncthreads per stage, loads post-barrier.
// RA=1: A raw fp32 (LDG+cvt+STS). RA=0: A half (cp.async).
// ---------------------------------------------------------------------------
#define LDTH 40
#define STAGE_H (128 * LDTH)
#define STAGE_BY (STAGE_H * 2)
#define GEMM_SMEM (6 * STAGE_BY)      // 61440 B

template <int RA, int HOUT>
__device__ __forceinline__ void gemm_body(
    const void* __restrict__ Av, const __half* __restrict__ Bt,
    void* __restrict__ Cv, int M, int N, int K, const float* __restrict__ bias,
    int m0, int n0, __half* sh)
{
    uint32_t sbase = smem_u32(sh);
    const int tid = threadIdx.x;
    const int wid = tid >> 5, lane = tid & 31;
    const int g = lane >> 2, tig = lane & 3;
    const int wm = wid & 1, wn = wid >> 1;

    const float*  Af = (const float*)Av;
    const __half* Ah = (const __half*)Av;

    const int lm = lane >> 3;
    const int arow = (lm & 1) * 8 + (lane & 7);
    const int acol = (lm >> 1) * 8;
    const int brow = ((lm >> 1) & 1) * 8 + (lane & 7);
    const int bcol = (lm & 1) * 8;

    float acc[4][4][4];
#pragma unroll
    for (int mi = 0; mi < 4; mi++)
#pragma unroll
        for (int ni = 0; ni < 4; ni++)
#pragma unroll
            for (int j = 0; j < 4; j++) acc[mi][ni][j] = 0.f;

    const int S = K / 32;

    const int lrow = tid >> 3;
    const int lc4 = tid & 7;
    float4 areg[4];
    auto ldg_A = [&](int s) {
        const float* Ag = Af + (size_t)m0 * K + s * 32;
#pragma unroll
        for (int i = 0; i < 4; i++) {
            int row = lrow + i * 32;
            areg[i] = *(const float4*)(Ag + (size_t)row * K + lc4 * 4);
        }
    };
    auto sts_A = [&](int s) {
        __half* aB = sh + (s % 3) * STAGE_H;
#pragma unroll
        for (int i = 0; i < 4; i++) {
            int row = lrow + i * 32;
            float4 v = areg[i];
            uint2 u = make_uint2(h2u(__floats2half2_rn(v.x, v.y)),
                                 h2u(__floats2half2_rn(v.z, v.w)));
            *(uint2*)(aB + row * LDTH + lc4 * 4) = u;
        }
    };
    const int hrow = tid >> 1;
    const int hc = tid & 1;
    auto cpa_A = [&](int s) {
        const __half* Ag = Ah + (size_t)m0 * K + s * 32;
        uint32_t aB = sbase + (s % 3) * STAGE_BY;
#pragma unroll
        for (int i = 0; i < 2; i++) {
            int c = hc * 2 + i;
            CP_ASYNC16(aB + (uint32_t)(hrow * 80 + c * 16),
                       Ag + (size_t)hrow * K + c * 8);
        }
    };
    auto cp_B = [&](int s) {
        const __half* Bg = Bt + (size_t)n0 * K + s * 32;
        uint32_t bB = sbase + 3 * STAGE_BY + (s % 3) * STAGE_BY;
#pragma unroll
        for (int i = 0; i < 2; i++) {
            int c = hc * 2 + i;
            CP_ASYNC16(bB + (uint32_t)(hrow * 80 + c * 16),
                       Bg + (size_t)hrow * K + c * 8);
        }
        CP_COMMIT();
    };

    if (RA) {
        ldg_A(0); cp_B(0); sts_A(0);
        ldg_A(1); cp_B(1); sts_A(1);
    } else {
        cpa_A(0); cp_B(0);
        cpa_A(1); cp_B(1);
    }

    for (int s = 0; s < S; s++) {
        if (s + 1 < S) CP_WAIT1();
        else           CP_WAIT0();
        __syncthreads();

        if (s + 2 < S) {
            if (RA) ldg_A(s + 2); else cpa_A(s + 2);
            cp_B(s + 2);
        }

        uint32_t Asb = sbase + (s % 3) * STAGE_BY + (wm * 64) * (LDTH * 2);
        uint32_t Bsb = sbase + 3 * STAGE_BY + (s % 3) * STAGE_BY + (wn * 32) * (LDTH * 2);

#pragma unroll
        for (int kk = 0; kk < 32; kk += 16) {
            uint32_t a[4][4], b[4][2];
#pragma unroll
            for (int mi = 0; mi < 4; mi++) {
                uint32_t addr = Asb + (uint32_t)(((mi * 16 + arow) * LDTH + kk + acol) * 2);
                LDSM_X4(a[mi][0], a[mi][1], a[mi][2], a[mi][3], addr);
            }
#pragma unroll
            for (int nj = 0; nj < 2; nj++) {
                uint32_t addr = Bsb + (uint32_t)(((nj * 16 + brow) * LDTH + kk + bcol) * 2);
                LDSM_X4(b[2 * nj][0], b[2 * nj][1], b[2 * nj + 1][0], b[2 * nj + 1][1], addr);
            }
#pragma unroll
            for (int mi = 0; mi < 4; mi++)
#pragma unroll
                for (int ni = 0; ni < 4; ni++)
                    mma_f16(acc[mi][ni], a[mi], b[ni]);
        }

        if (RA && (s + 2 < S)) sts_A(s + 2);
    }

#pragma unroll
    for (int mi = 0; mi < 4; mi++) {
        int r0 = m0 + wm * 64 + mi * 16 + g;
#pragma unroll
        for (int ni = 0; ni < 4; ni++) {
            int c = n0 + wn * 32 + ni * 8 + 2 * tig;
            if (HOUT) {
                __half* Ch = (__half*)Cv;
                *(__half2*)(Ch + (size_t)r0 * N + c) =
                    __floats2half2_rn(acc[mi][ni][0], acc[mi][ni][1]);
                *(__half2*)(Ch + (size_t)(r0 + 8) * N + c) =
                    __floats2half2_rn(acc[mi][ni][2], acc[mi][ni][3]);
            } else {
                float* Cf = (float*)Cv;
                float b0 = bias ? bias[c] : 0.f;
                float b1 = bias ? bias[c + 1] : 0.f;
                *(float2*)(Cf + (size_t)r0 * N + c) =
                    make_float2(acc[mi][ni][0] + b0, acc[mi][ni][1] + b1);
                *(float2*)(Cf + (size_t)(r0 + 8) * N + c) =
                    make_float2(acc[mi][ni][2] + b0, acc[mi][ni][3] + b1);
            }
        }
    }
}

// Fused q-proj + kv-proj: bid < 512 -> q GEMM tiles, else kv GEMM tiles.
#define Q_CTAS 512      // (8192/128) * (1024/128)
#define KV_CTAS 2048    // (16384/128) * (2048/128)

__global__ __launch_bounds__(256, 2) void proj_gemm(
    const float* __restrict__ query, const __half* __restrict__ wqT,
    __half* __restrict__ qout,
    const float* __restrict__ context, const __half* __restrict__ wkvT,
    __half* __restrict__ kvout)
{
    extern __shared__ __half sh[];
    int bid = blockIdx.x;
    if (bid < Q_CTAS) {
        int nt = bid & 7, mt = bid >> 3;
        gemm_body<1, 1>(query, wqT, qout, BB * NQ, INNER, QD, nullptr,
                        mt * 128, nt * 128, sh);
    } else {
        int b2 = bid - Q_CTAS;
        int nt = b2 & 15, mt = b2 >> 4;
        gemm_body<1, 1>(context, wkvT, kvout, BB * NKV, 2 * INNER, CD, nullptr,
                        mt * 128, nt * 128, sh);
    }
}

// out-proj (half A via cp.async, fp32 C + bias)
__global__ __launch_bounds__(256, 2) void out_gemm(
    const __half* __restrict__ att, const __half* __restrict__ woutT,
    float* __restrict__ out, const float* __restrict__ bias)
{
    extern __shared__ __half sh[];
    int nt = blockIdx.x, mt = blockIdx.y;
    gemm_body<0, 0>(att, woutT, out, BB * NQ, QD, INNER, bias,
                    mt * 128, nt * 128, sh);
}

// ---------------------------------------------------------------------------
// fp16 tensor-core flash attention (R9/R13/R14 best).
// ---------------------------------------------------------------------------
#define ASTH 72
#define ATT_SMEM (4 * 64 * ASTH * 2)   // 36864 bytes
#define QSCALE (0.125f * 1.4426950408889634f)

__global__ __launch_bounds__(256) void attn_mma(
    const __half* __restrict__ qb, const __half* __restrict__ kvb,
    __half* __restrict__ ob)
{
    extern __shared__ __half sha[];
    uint32_t sbase = smem_u32(sha);

    const int tid = threadIdx.x;
    const int w = tid >> 5, lane = tid & 31;
    const int g = lane >> 2, tig = lane & 3;
    const int b = blockIdx.y >> 4, h = blockIdx.y & 15;
    const int q0 = blockIdx.x * 128;

    const int lm = lane >> 3;
    const int brow = ((lm >> 1) & 1) * 8 + (lane & 7);
    const int bcol = (lm & 1) * 8;

    const __half* kbase = kvb + (size_t)b * NKV * (2 * INNER) + h * HD;
    const __half* vbase = kbase + INNER;

    uint32_t qf[4][4];
    {
        const __half* Qp = qb + ((size_t)(b * NQ + q0 + w * 16 + g)) * INNER + h * HD;
        const __half2 qs = __float2half2_rn(QSCALE);
#pragma unroll
        for (int kt = 0; kt < 4; kt++) {
            int d = kt * 16 + 2 * tig;
            qf[kt][0] = h2u(__hmul2(*(const __half2*)(Qp + d), qs));
            qf[kt][1] = h2u(__hmul2(*(const __half2*)(Qp + 8 * INNER + d), qs));
            qf[kt][2] = h2u(__hmul2(*(const __half2*)(Qp + d + 8), qs));
            qf[kt][3] = h2u(__hmul2(*(const __half2*)(Qp + 8 * INNER + d + 8), qs));
        }
    }

    float o[8][4];
#pragma unroll
    for (int dt = 0; dt < 8; dt++)
#pragma unroll
        for (int j = 0; j < 4; j++) o[dt][j] = 0.f;
    float l_a = 0.f, l_b = 0.f;

    auto stage_load = [&](int s) {
        const int buf = s & 1;
        const int kv0 = s * 64;
#pragma unroll
        for (int i = 0; i < 4; i++) {
            int slot = tid + i * 256;
            int isK = slot < 512;
            int ls = slot & 511;
            int row = ls >> 3, c8 = ls & 7;
            const __half* src = (isK ? kbase : vbase) + (size_t)(kv0 + row) * (2 * INNER) + c8 * 8;
            uint32_t dst = sbase + (uint32_t)(((isK ? buf : 2 + buf) * 64 + row) * ASTH * 2 + c8 * 16);
            CP_ASYNC16(dst, src);
        }
        CP_COMMIT();
    };

    const int S = NKV / 64;   // 32
    stage_load(0);

    const int vrow = lane & 15;
    const int vcol = ((lane >> 4) & 1) * 8;

    for (int s = 0; s < S; s++) {
        CP_WAIT0();
        __syncthreads();
        if (s + 1 < S) stage_load(s + 1);

        uint32_t Ksb = sbase + (s & 1) * 64 * ASTH * 2;
        const __half* Vsb = sha + (2 + (s & 1)) * 64 * ASTH;

        float sacc[8][4];
#pragma unroll
        for (int nt = 0; nt < 8; nt++)
#pragma unroll
            for (int j = 0; j < 4; j++) sacc[nt][j] = 0.f;

#pragma unroll
        for (int kt = 0; kt < 4; kt++) {
#pragma unroll
            for (int nj = 0; nj < 4; nj++) {
                uint32_t addr = Ksb + (uint32_t)(((nj * 16 + brow) * ASTH + kt * 16 + bcol) * 2);
                uint32_t b0, b1, b2, b3;
                LDSM_X4(b0, b1, b2, b3, addr);
                uint32_t bA[2] = { b0, b1 };
                uint32_t bB2[2] = { b2, b3 };
                mma_f16(sacc[2 * nj], qf[kt], bA);
                mma_f16(sacc[2 * nj + 1], qf[kt], bB2);
            }
        }

        uint32_t ph[8][2];
#pragma unroll
        for (int nt = 0; nt < 8; nt++) {
            float p0 = ex2(sacc[nt][0]);
            float p1 = ex2(sacc[nt][1]);
            float p2 = ex2(sacc[nt][2]);
            float p3 = ex2(sacc[nt][3]);
            l_a += p0 + p1;
            l_b += p2 + p3;
            ph[nt][0] = h2u(__floats2half2_rn(p0, p1));
            ph[nt][1] = h2u(__floats2half2_rn(p2, p3));
        }

#pragma unroll
        for (int kt = 0; kt < 4; kt++) {
            uint32_t a[4] = { ph[2 * kt][0], ph[2 * kt][1],
                              ph[2 * kt + 1][0], ph[2 * kt + 1][1] };
#pragma unroll
            for (int dd = 0; dd < 4; dd++) {
                uint32_t addr = smem_u32(Vsb + (kt * 16 + vrow) * ASTH + dd * 16 + vcol);
                uint32_t r0, r1, r2, r3;
                LDSM_X4_T(r0, r1, r2, r3, addr);
                uint32_t b01[2] = { r0, r1 };
                uint32_t b23[2] = { r2, r3 };
                mma_f16(o[2 * dd], a, b01);
                mma_f16(o[2 * dd + 1], a, b23);
            }
        }
    }

    l_a += __shfl_xor_sync(0xffffffffu, l_a, 1);
    l_a += __shfl_xor_sync(0xffffffffu, l_a, 2);
    l_b += __shfl_xor_sync(0xffffffffu, l_b, 1);
    l_b += __shfl_xor_sync(0xffffffffu, l_b, 2);
    const float inv_a = 1.f / l_a, inv_b = 1.f / l_b;

    __half* oa = ob + ((size_t)(b * NQ + q0 + w * 16 + g)) * INNER + h * HD;
    __half* obp = oa + 8 * INNER;
#pragma unroll
    for (int dt = 0; dt < 8; dt++) {
        int c = dt * 8 + 2 * tig;
        *(__half2*)(oa + c) = __floats2half2_rn(o[dt][0] * inv_a, o[dt][1] * inv_a);
        *(__half2*)(obp + c) = __floats2half2_rn(o[dt][2] * inv_b, o[dt][3] * inv_b);
    }
}

// ---------------------------------------------------------------------------
extern "C" void kernel_launch(void* const* d_in, const int* in_sizes, int n_in,
                              void* d_out, int out_size)
{
    const float* query   = (const float*)d_in[0];
    const float* context = (const float*)d_in[1];
    const float* w_q     = (const float*)d_in[2];
    const float* w_kv    = (const float*)d_in[3];
    const float* w_out   = (const float*)d_in[4];
    const float* b_out   = (const float*)d_in[5];
    float* out = (float*)d_out;

    __half *q, *kv, *att, *wqT, *wkvT, *woutT;
    cudaGetSymbolAddress((void**)&q, g_q);
    cudaGetSymbolAddress((void**)&kv, g_kv);
    cudaGetSymbolAddress((void**)&att, g_att);
    cudaGetSymbolAddress((void**)&wqT, g_wqT);
    cudaGetSymbolAddress((void**)&wkvT, g_wkvT);
    cudaGetSymbolAddress((void**)&woutT, g_woutT);

    cudaFuncSetAttribute(proj_gemm, cudaFuncAttributeMaxDynamicSharedMemorySize, GEMM_SMEM);
    cudaFuncSetAttribute(out_gemm, cudaFuncAttributeMaxDynamicSharedMemorySize, GEMM_SMEM);
    cudaFuncSetAttribute(attn_mma, cudaFuncAttributeMaxDynamicSharedMemorySize, ATT_SMEM);

    // fused weight transposes (fp16, [N,K])
    transpose3_k<<<dim3(64, 32, 3), dim3(32, 8)>>>(w_q, wqT, w_kv, wkvT, w_out, woutT);

    // fused q-proj + kv-proj
    proj_gemm<<<Q_CTAS + KV_CTAS, 256, GEMM_SMEM>>>(query, wqT, q, context, wkvT, kv);

    // attention (all-fp16 operands, fp32 accum; emits half att)
    attn_mma<<<dim3(NQ / 128, BB * NH), 256, ATT_SMEM>>>(q, kv, att);

    // out = att @ w_out + b (fp32 out)
    out_gemm<<<dim3(QD / 128, BB * NQ / 128), 256, GEMM_SMEM>>>(att, woutT, out, b_out);
}